// round 13
// baseline (speedup 1.0000x reference)
#include <cuda_runtime.h>
#include <cuda_fp16.h>

#define B_ 32
#define C_ 512
#define L_ 2048
#define F_ 1025
#define NE 8
#define GROUPS 64          // blocks per batch; each block does 8 rows
#define TPB 128            // 2 row-slots x 64 threads

// ---------------- static device scratch ----------------
__device__ float2 g_tw1024[1024];     // e^{-2*pi*i*j/1024}
__device__ float2 g_tw2048[1025];     // e^{-2*pi*i*f/2048}
__device__ __align__(16) float g_mean[B_*L_];
__device__ __align__(16) float g_rstd[B_*L_];
__device__ float  g_lp[B_*GROUPS*NE]; // per-(batch,row-group) partial logits
__device__ __half2 g_spec[(size_t)B_*C_*1024];  // cached spectra (fp16), slot-linear

// ---------------- complex helpers ----------------
__device__ __forceinline__ float2 cmul(float2 a, float2 b){
  return make_float2(a.x*b.x - a.y*b.y, a.x*b.y + a.y*b.x);
}
__device__ __forceinline__ float2 cadd(float2 a, float2 b){ return make_float2(a.x+b.x, a.y+b.y); }
__device__ __forceinline__ float2 csub(float2 a, float2 b){ return make_float2(a.x-b.x, a.y-b.y); }
__device__ __forceinline__ float2 cmnegi(float2 a){ return make_float2(a.y, -a.x); } // *(-i)

__device__ __forceinline__ int br2(int x){ return ((x&1)<<1)|(x>>1); }
// spectrum slot for frequency f = k1 + 16*k2a + 256*kb:
// slot = k2a*66 + 4*k1 + br2(kb)
__device__ __forceinline__ int slotf(int f){
  return ((f>>4)&15)*66 + ((f&15)<<2) + br2(f>>8);
}

// forward 16-point DFT in registers (natural in/out), W16 = e^{-2pi i/16}
__device__ __forceinline__ void dft16(float2* a){
  const float C1 = 0.92387953251128674f, S1 = 0.38268343236508977f, R2 = 0.70710678118654752f;
  float2 v[16];
  #pragma unroll
  for (int ja=0; ja<4; ja++){
    float2 p0=a[ja], p1=a[ja+4], p2=a[ja+8], p3=a[ja+12];
    float2 t0=cadd(p0,p2), t1=csub(p0,p2), t2=cadd(p1,p3), t3=csub(p1,p3);
    v[ja*4+0]=cadd(t0,t2);
    v[ja*4+1]=make_float2(t1.x+t3.y, t1.y-t3.x);   // t1 - i t3
    v[ja*4+2]=csub(t0,t2);
    v[ja*4+3]=make_float2(t1.x-t3.y, t1.y+t3.x);   // t1 + i t3
  }
  const float2 W1=make_float2( C1,-S1), W2=make_float2( R2,-R2), W3=make_float2( S1,-C1),
               W6=make_float2(-R2,-R2), W9=make_float2(-C1, S1);
  v[5]=cmul(v[5],W1);   v[6]=cmul(v[6],W2);   v[7]=cmul(v[7],W3);
  v[9]=cmul(v[9],W2);   v[10]=cmnegi(v[10]);  v[11]=cmul(v[11],W6);
  v[13]=cmul(v[13],W3); v[14]=cmul(v[14],W6); v[15]=cmul(v[15],W9);
  #pragma unroll
  for (int k=0;k<4;k++){
    float2 p0=v[k], p1=v[4+k], p2=v[8+k], p3=v[12+k];
    float2 t0=cadd(p0,p2), t1=csub(p0,p2), t2=cadd(p1,p3), t3=csub(p1,p3);
    a[k]    =cadd(t0,t2);
    a[k+4]  =make_float2(t1.x+t3.y, t1.y-t3.x);
    a[k+8]  =csub(t0,t2);
    a[k+12] =make_float2(t1.x-t3.y, t1.y+t3.x);
  }
}

// p[k] = w^k, log-depth ladder (max 3 chained cmuls)
__device__ __forceinline__ void build_pows(float2 w, float2* p){
  p[0]=make_float2(1.f,0.f); p[1]=w;
  p[2]=cmul(w,w); p[3]=cmul(p[2],w); p[4]=cmul(p[2],p[2]);
  p[5]=cmul(p[4],p[1]); p[6]=cmul(p[4],p[2]); p[7]=cmul(p[4],p[3]);
  p[8]=cmul(p[4],p[4]);
  #pragma unroll
  for (int k=9;k<16;k++) p[k]=cmul(p[8],p[k-8]);
}

__device__ __forceinline__ float2 shflx(float2 v, int m){
  float2 o;
  o.x = __shfl_xor_sync(0xffffffffu, v.x, m);
  o.y = __shfl_xor_sync(0xffffffffu, v.y, m);
  return o;
}

// Forward 1024-pt FFT. In: a[j] = z[64j+r]. Out: a[k2a] = Z[k1+16*k2a+256*br2(q)],
// k1=r>>2, q=r&3. T: >=1056 float2 scratch. 2 block syncs.
__device__ __forceinline__ void fft1024(float2* a, float2* T, int r, float2 wr, float2 wq){
  float2 p[16];
  dft16(a);
  build_pows(wr, p);
  #pragma unroll
  for (int k=1;k<16;k++) a[k]=cmul(a[k],p[k]);
  #pragma unroll
  for (int k=0;k<16;k++) T[k*66+r]=a[k];
  __syncthreads();
  int k1=r>>2, q=r&3;
  #pragma unroll
  for (int m=0;m<16;m++) a[m]=T[k1*66+4*m+q];
  __syncthreads();
  dft16(a);
  build_pows(wq, p);
  #pragma unroll
  for (int k=1;k<16;k++) a[k]=cmul(a[k],p[k]);
  bool b2=(q&2)!=0, b1=(q&1)!=0, b3=(q==3);
  #pragma unroll
  for (int k=0;k<16;k++){
    float2 v=a[k];
    float2 pp=shflx(v,2);
    float2 A = b2 ? csub(pp,v) : cadd(v,pp);
    A = b3 ? cmnegi(A) : A;
    float2 p2=shflx(A,1);
    a[k] = b1 ? csub(p2,A) : cadd(A,p2);
  }
}

// ---------------- K1: stats, float2 loads, 8-way channel-split (+ twiddles) ----------------
__global__ __launch_bounds__(256) void k_stats(const float* __restrict__ x){
  __shared__ float2 ss0[256];
  __shared__ float2 ss1[256];
  int t = threadIdx.x;
  int lq = t & 31, cs = t >> 5;          // 32 l-pairs x 8 channel slices (64 ch each)
  int b = blockIdx.y;
  if (b == 0 && blockIdx.x < 8){   // 8 blocks * 256 = 2048 threads build tables
    int tg = blockIdx.x*256 + t;
    if (tg < 1024){
      double sd, cd; sincospi(-2.0*(double)tg/1024.0, &sd, &cd);
      g_tw1024[tg] = make_float2((float)cd, (float)sd);
    } else {
      int f = tg - 1024;
      double sd, cd; sincospi(-(double)f/1024.0, &sd, &cd);
      g_tw2048[f] = make_float2((float)cd, (float)sd);
    }
    if (tg == 0) g_tw2048[1024] = make_float2(-1.f, 0.f);
  }
  const float2* p = (const float2*)(x + (size_t)b*C_*L_ + (size_t)cs*64*L_)
                    + blockIdx.x*32 + lq;       // float2 index within row
  float2 s  = make_float2(0.f,0.f);
  float2 s2 = make_float2(0.f,0.f);
  #pragma unroll 8
  for (int c = 0; c < 64; c++){
    float2 v = p[(size_t)c*(L_/2)];
    s.x  += v.x;     s.y  += v.y;
    s2.x += v.x*v.x; s2.y += v.y*v.y;
  }
  ss0[t] = s; ss1[t] = s2;
  __syncthreads();
  if (cs == 0){
    float Sx=0.f, Sy=0.f, S2x=0.f, S2y=0.f;
    #pragma unroll
    for (int k=0;k<8;k++){
      float2 a0 = ss0[k*32+lq], a1 = ss1[k*32+lq];
      Sx += a0.x; Sy += a0.y; S2x += a1.x; S2y += a1.y;
    }
    float mx = Sx * (1.0f/C_);
    float my = Sy * (1.0f/C_);
    float vx = (S2x - Sx*Sx*(1.0f/C_)) * (1.0f/(C_-1)) + 1e-5f;
    float vy = (S2y - Sy*Sy*(1.0f/C_)) * (1.0f/(C_-1)) + 1e-5f;
    int li = blockIdx.x*32 + lq;                // float2 index in l
    ((float2*)(g_mean + b*L_))[li] = make_float2(mx, my);
    ((float2*)(g_rstd + b*L_))[li] = make_float2(rsqrtf(vx), rsqrtf(vy));
  }
}

// ---------------- K2: spectra -> fp16 cache + |X| sums -> partial gating logits ----------------
__global__ __launch_bounds__(TPB) void k_spec(const float* __restrict__ x,
                                              const float* __restrict__ gw){
  extern __shared__ float2 smraw[];
  float2* T   = smraw;            // 2*1088
  float2* m2  = T + 2176;         // 1024
  float2* r2v = m2 + 1024;        // 1024
  float*  acc = (float*)(r2v + 1024); // 1025
  __shared__ float sred[NE][4];
  int t=threadIdx.x, s=t>>6, r=t&63;
  int b=blockIdx.y, grp=blockIdx.x;
  float2* Ts = T + s*1088;
  const float2* gm2=(const float2*)(g_mean + b*L_);
  const float2* gr2=(const float2*)(g_rstd + b*L_);
  for (int i=t;i<1024;i+=TPB){ m2[i]=gm2[i]; r2v[i]=gr2[i]; }
  for (int i=t;i<F_;i+=TPB) acc[i]=0.f;
  float2 wr=g_tw1024[r];
  float2 wq=g_tw1024[(r&3)<<4];
  __syncthreads();

  for (int it=0; it<4; it++){
    int c = grp*8 + it*2 + s;
    size_t row = (size_t)(b*C_+c);
    const float2* xr = (const float2*)(x + row*L_);
    float2 a[16];
    #pragma unroll
    for (int j=0;j<16;j++){
      int n=(j<<6)+r;
      float2 v=xr[n], mm=m2[n], rr=r2v[n];
      a[j]=make_float2((v.x-mm.x)*rr.x,(v.y-mm.y)*rr.y);
    }
    fft1024(a, Ts, r, wr, wq);
    // spectrum -> smem (own slots) AND fp16 gmem cache (coalesced, slot-linear)
    __half2* gsr = g_spec + row*1024;
    #pragma unroll
    for (int k=0;k<16;k++){
      Ts[k*66+r]=a[k];
      gsr[(k<<6)+r]=__float22half2_rn(a[k]);
    }
    __syncthreads();

    #pragma unroll
    for (int i=0;i<4;i++){
      int f = t + (i<<7);
      if (f==0){
        #pragma unroll
        for (int s2=0;s2<2;s2++){
          float2 z0=T[s2*1088 + 0];
          acc[0]    += fabsf(z0.x+z0.y);
          acc[1024] += fabsf(z0.x-z0.y);
          float2 zh=T[s2*1088 + 1];           // slotf(512)=1
          acc[512]  += sqrtf(zh.x*zh.x+zh.y*zh.y);
        }
      } else {
        int pa=slotf(f), pb=slotf(1024-f);
        float2 W=g_tw2048[f];
        float sa=0.f, sb=0.f;
        #pragma unroll
        for (int s2=0;s2<2;s2++){
          float2 Zf=T[s2*1088+pa], Zg=T[s2*1088+pb];
          float Ex=0.5f*(Zf.x+Zg.x), Ey=0.5f*(Zf.y-Zg.y);
          float Ox=0.5f*(Zf.y+Zg.y), Oy=-0.5f*(Zf.x-Zg.x);
          float WOx=Ox*W.x-Oy*W.y, WOy=Ox*W.y+Oy*W.x;
          float Xax=Ex+WOx, Xay=Ey+WOy;
          float Xbx=Ex-WOx, Xby=Ey-WOy;
          sa += sqrtf(Xax*Xax+Xay*Xay);
          sb += sqrtf(Xbx*Xbx+Xby*Xby);
        }
        acc[f]      += sa;
        acc[1024-f] += sb;
      }
    }
    __syncthreads();
  }

  // partial gating logits for this row-group: pe[e] = sum_f acc[f]*gw[e,f]
  float pe[NE];
  #pragma unroll
  for (int e=0;e<NE;e++) pe[e]=0.f;
  for (int f=t; f<F_; f+=TPB){
    float gi=acc[f];
    #pragma unroll
    for (int e=0;e<NE;e++) pe[e]+=gi*gw[e*F_+f];
  }
  #pragma unroll
  for (int e=0;e<NE;e++){
    float v=pe[e];
    #pragma unroll
    for (int o=16;o;o>>=1) v += __shfl_xor_sync(0xffffffffu, v, o);
    if ((t&31)==0) sred[e][t>>5]=v;
  }
  __syncthreads();
  if (t < NE){
    float sum = sred[t][0]+sred[t][1]+sred[t][2]+sred[t][3];
    g_lp[(b*GROUPS+grp)*NE + t] = sum;
  }
}

// ---------------- K3: inline gating -> cached fp16 spectrum -> filter -> inv FFT -> denorm ----------------
__global__ __launch_bounds__(TPB) void k_main(const float* __restrict__ bb,
                                              const float* __restrict__ gb,
                                              float* __restrict__ out){
  extern __shared__ float2 smraw[];
  float2* T   = smraw;            // 2*1088 (spectrum / transpose / time staging)
  float2* N   = T + 2176;         // 2*1024 (conj(Z') natural layout)
  float2* m2  = N + 2048;         // 1024
  float2* r2v = m2 + 1024;        // 1024
  float*  sw  = (float*)(r2v + 1024); // 1025
  __shared__ float spart[64];
  __shared__ float ssc[NE];
  __shared__ int   sidx[NE+1];
  int t=threadIdx.x, s=t>>6, r=t&63;
  int b=blockIdx.y, grp=blockIdx.x;
  float2* Ts = T + s*1088;
  float2* Nsl = N + s*1024;
  const float2* gm2=(const float2*)(g_mean + b*L_);
  const float2* gr2=(const float2*)(g_rstd + b*L_);
  for (int i=t;i<1024;i+=TPB){ m2[i]=gm2[i]; r2v[i]=gr2[i]; }
  // gating reduction: 64 threads, each sums 8 groups for one expert
  if (t < 64){
    int e = t & 7, gc = t >> 3;
    float sacc = 0.f;
    #pragma unroll
    for (int g=0; g<8; g++) sacc += g_lp[(b*GROUPS + gc*8 + g)*NE + e];
    spart[t] = sacc;
  }
  float2 wr=g_tw1024[r];
  float2 wq=g_tw1024[(r&3)<<4];
  __syncthreads();
  if (t == 0){
    float lg[NE]; float mx=-1e30f;
    #pragma unroll
    for (int e=0;e<NE;e++){
      float sm=0.f;
      #pragma unroll
      for (int gc=0;gc<8;gc++) sm += spart[gc*8+e];
      lg[e]=sm*(1.0f/C_)+gb[e];
      mx=fmaxf(mx,lg[e]);
    }
    float sum=0.f;
    #pragma unroll
    for (int e=0;e<NE;e++){ lg[e]=expf(lg[e]-mx); sum+=lg[e]; }
    float inv=1.0f/sum;
    #pragma unroll
    for (int e=0;e<NE;e++) ssc[e]=lg[e]*inv;
    float bnd[NE-1];
    #pragma unroll
    for (int i=0;i<NE-1;i++) bnd[i]=1.0f/(1.0f+expf(-bb[i]));
    for (int i=1;i<NE-1;i++){            // ascending insertion sort
      float key=bnd[i]; int k=i-1;
      while (k>=0 && bnd[k]>key){ bnd[k+1]=bnd[k]; k--; }
      bnd[k+1]=key;
    }
    sidx[0]=0;
    #pragma unroll
    for (int i=0;i<NE-1;i++) sidx[i+1]=(int)(bnd[i]*(float)F_);
    sidx[NE]=F_;
  }
  __syncthreads();
  for (int f=t; f<F_; f+=TPB){
    float w=0.f;
    #pragma unroll
    for (int e=0;e<NE;e++)
      if (f>=sidx[e] && f<sidx[e+1]) w+=ssc[e];
    sw[f]=w;
  }
  __syncthreads();

  const float sc = 1.0f/2048.0f;  // 1/2 (real pack) * 1/1024 (ifft)
  for (int it=0; it<4; it++){
    int c = grp*8 + it*2 + s;
    size_t row = (size_t)(b*C_+c);
    // load cached fp16 spectrum: coalesced gmem -> conflict-free smem columns
    const __half2* gsr = g_spec + row*1024;
    #pragma unroll
    for (int k=0;k<16;k++) Ts[k*66+r] = __half22float2(gsr[(k<<6)+r]);
    __syncthreads();

    // filter: unpack -> Y=w*X -> repack Z' -> write conj(Z') to N (natural order)
    #pragma unroll
    for (int i=0;i<4;i++){
      int f = t + (i<<7);
      if (f==0){
        #pragma unroll
        for (int s2=0;s2<2;s2++){
          float2 z0=T[s2*1088 + 0];
          float X0=z0.x+z0.y, X1=z0.x-z0.y;
          float Y0=sw[0]*X0, Y1=sw[1024]*X1;
          N[s2*1024 + 0]   = make_float2(sc*(Y0+Y1), -sc*(Y0-Y1));
          float wh = sw[512]*(1.0f/1024.0f);
          float2 zh=T[s2*1088 + 1];           // slotf(512)=1
          N[s2*1024 + 512] = make_float2(zh.x*wh, -zh.y*wh);
        }
      } else {
        int pa=slotf(f), pb=slotf(1024-f);
        float wa=sw[f], wb=sw[1024-f];
        float2 W =g_tw2048[f];
        float2 W2=g_tw2048[1024-f];
        #pragma unroll
        for (int s2=0;s2<2;s2++){
          float2 Zf=T[s2*1088+pa], Zg=T[s2*1088+pb];
          float Ex=0.5f*(Zf.x+Zg.x), Ey=0.5f*(Zf.y-Zg.y);
          float Ox=0.5f*(Zf.y+Zg.y), Oy=-0.5f*(Zf.x-Zg.x);
          float WOx=Ox*W.x-Oy*W.y, WOy=Ox*W.y+Oy*W.x;
          float Yax=wa*(Ex+WOx), Yay=wa*(Ey+WOy);
          float Ybx=wb*(Ex-WOx), Yby=wb*(-(Ey-WOy));
          float Ax=Yax+Ybx, Ay=Yay-Yby;
          float Bx=Yax-Ybx, By=Yay+Yby;
          float Cx=Bx*W.x+By*W.y, Cy=By*W.x-Bx*W.y;
          N[s2*1024 + f]      = make_float2(sc*(Ax-Cy), -sc*(Ay+Cx));
          float A2x=Ybx+Yax, A2y=Yby-Yay;
          float B2x=Ybx-Yax, B2y=Yby+Yay;
          float C2x=B2x*W2.x+B2y*W2.y, C2y=B2y*W2.x-B2x*W2.y;
          N[s2*1024 + 1024-f] = make_float2(sc*(A2x-C2y), -sc*(A2y+C2x));
        }
      }
    }
    __syncthreads();

    // inverse FFT via conjugation trick: ifft(Z') = conj(fft(conj(Z')))
    float2 a[16];
    #pragma unroll
    for (int j=0;j<16;j++) a[j]=Nsl[(j<<6)+r];
    fft1024(a, Ts, r, wr, wq);
    // stage time samples (conjugated) into Ts at padded natural index
    {
      int k1=r>>2, kb=br2(r&3);
      int base = k1 + 264*kb;                  // n + 8*(n>>8), n = k1+16k+256kb
      #pragma unroll
      for (int k=0;k<16;k++)
        Ts[base + (k<<4)] = make_float2(a[k].x, -a[k].y);
    }
    __syncthreads();

    // de-normalize + coalesced store (stats from smem)
    float4* orow = (float4*)(out + row*L_);
    #pragma unroll
    for (int cc=0; cc<8; cc++){
      int i4 = (cc<<6) + r;                    // float4 index in row
      int n0 = i4<<1;
      int u  = n0 + ((n0>>8)<<3);
      float2 y0=Ts[u], y1=Ts[u+1];
      float2 mm0=m2[n0], mm1=m2[n0+1], rr0=r2v[n0], rr1=r2v[n0+1];
      float4 o;
      o.x=__fdividef(y0.x, rr0.x)+mm0.x;
      o.y=__fdividef(y0.y, rr0.y)+mm0.y;
      o.z=__fdividef(y1.x, rr1.x)+mm1.x;
      o.w=__fdividef(y1.y, rr1.y)+mm1.y;
      orow[i4]=o;
    }
    __syncthreads();
  }
}

// ---------------- launch ----------------
extern "C" void kernel_launch(void* const* d_in, const int* in_sizes, int n_in,
                              void* d_out, int out_size){
  const float* x  = (const float*)d_in[0];
  const float* bb = (const float*)d_in[1];
  const float* gw = (const float*)d_in[2];
  const float* gb = (const float*)d_in[3];
  float* out = (float*)d_out;

  const int SM_SPEC = (2176+1024+1024)*sizeof(float2) + F_*sizeof(float);        // ~37.9KB
  const int SM_MAIN = (2176+2048+1024+1024)*sizeof(float2) + F_*sizeof(float);   // ~54.3KB
  cudaFuncSetAttribute(k_spec, cudaFuncAttributeMaxDynamicSharedMemorySize, SM_SPEC);
  cudaFuncSetAttribute(k_main, cudaFuncAttributeMaxDynamicSharedMemorySize, SM_MAIN);

  k_stats<<<dim3(L_/64, B_), 256>>>(x);
  k_spec<<<dim3(GROUPS, B_), TPB, SM_SPEC>>>(x, gw);
  k_main<<<dim3(GROUPS, B_), TPB, SM_MAIN>>>(bb, gb, out);
}

// round 15
// speedup vs baseline: 1.4692x; 1.4692x over previous
#include <cuda_runtime.h>
#include <cuda_fp16.h>

#define B_ 32
#define C_ 512
#define L_ 2048
#define F_ 1025
#define NE 8
#define GROUPS 64          // blocks per batch; each block does 8 rows
#define TPB 128            // 2 row-slots x 64 threads

// ---------------- static device scratch ----------------
__device__ float2 g_tw1024[1024];     // e^{-2*pi*i*j/1024}
__device__ float2 g_tw2048[1025];     // e^{-2*pi*i*f/2048}
__device__ float  g_mean[B_*L_];
__device__ float  g_rstd[B_*L_];
__device__ float  g_lp[B_*GROUPS*NE]; // per-(batch,row-group) partial logits
__device__ __half2 g_spec[(size_t)B_*C_*1024];  // cached spectra (fp16), slot-linear

// ---------------- complex helpers ----------------
__device__ __forceinline__ float2 cmul(float2 a, float2 b){
  return make_float2(a.x*b.x - a.y*b.y, a.x*b.y + a.y*b.x);
}
__device__ __forceinline__ float2 cadd(float2 a, float2 b){ return make_float2(a.x+b.x, a.y+b.y); }
__device__ __forceinline__ float2 csub(float2 a, float2 b){ return make_float2(a.x-b.x, a.y-b.y); }
__device__ __forceinline__ float2 cmnegi(float2 a){ return make_float2(a.y, -a.x); } // *(-i)

__device__ __forceinline__ int br2(int x){ return ((x&1)<<1)|(x>>1); }
// spectrum slot for frequency f = k1 + 16*k2a + 256*kb:
// slot = k2a*66 + 4*k1 + br2(kb)
__device__ __forceinline__ int slotf(int f){
  return ((f>>4)&15)*66 + ((f&15)<<2) + br2(f>>8);
}

// forward 16-point DFT in registers (natural in/out), W16 = e^{-2pi i/16}
__device__ __forceinline__ void dft16(float2* a){
  const float C1 = 0.92387953251128674f, S1 = 0.38268343236508977f, R2 = 0.70710678118654752f;
  float2 v[16];
  #pragma unroll
  for (int ja=0; ja<4; ja++){
    float2 p0=a[ja], p1=a[ja+4], p2=a[ja+8], p3=a[ja+12];
    float2 t0=cadd(p0,p2), t1=csub(p0,p2), t2=cadd(p1,p3), t3=csub(p1,p3);
    v[ja*4+0]=cadd(t0,t2);
    v[ja*4+1]=make_float2(t1.x+t3.y, t1.y-t3.x);   // t1 - i t3
    v[ja*4+2]=csub(t0,t2);
    v[ja*4+3]=make_float2(t1.x-t3.y, t1.y+t3.x);   // t1 + i t3
  }
  const float2 W1=make_float2( C1,-S1), W2=make_float2( R2,-R2), W3=make_float2( S1,-C1),
               W6=make_float2(-R2,-R2), W9=make_float2(-C1, S1);
  v[5]=cmul(v[5],W1);   v[6]=cmul(v[6],W2);   v[7]=cmul(v[7],W3);
  v[9]=cmul(v[9],W2);   v[10]=cmnegi(v[10]);  v[11]=cmul(v[11],W6);
  v[13]=cmul(v[13],W3); v[14]=cmul(v[14],W6); v[15]=cmul(v[15],W9);
  #pragma unroll
  for (int k=0;k<4;k++){
    float2 p0=v[k], p1=v[4+k], p2=v[8+k], p3=v[12+k];
    float2 t0=cadd(p0,p2), t1=csub(p0,p2), t2=cadd(p1,p3), t3=csub(p1,p3);
    a[k]    =cadd(t0,t2);
    a[k+4]  =make_float2(t1.x+t3.y, t1.y-t3.x);
    a[k+8]  =csub(t0,t2);
    a[k+12] =make_float2(t1.x-t3.y, t1.y+t3.x);
  }
}

// p[k] = w^k, log-depth ladder (max 3 chained cmuls)
__device__ __forceinline__ void build_pows(float2 w, float2* p){
  p[0]=make_float2(1.f,0.f); p[1]=w;
  p[2]=cmul(w,w); p[3]=cmul(p[2],w); p[4]=cmul(p[2],p[2]);
  p[5]=cmul(p[4],p[1]); p[6]=cmul(p[4],p[2]); p[7]=cmul(p[4],p[3]);
  p[8]=cmul(p[4],p[4]);
  #pragma unroll
  for (int k=9;k<16;k++) p[k]=cmul(p[8],p[k-8]);
}

__device__ __forceinline__ float2 shflx(float2 v, int m){
  float2 o;
  o.x = __shfl_xor_sync(0xffffffffu, v.x, m);
  o.y = __shfl_xor_sync(0xffffffffu, v.y, m);
  return o;
}

// Forward 1024-pt FFT. In: a[j] = z[64j+r]. Out: a[k2a] = Z[k1+16*k2a+256*br2(q)],
// k1=r>>2, q=r&3. T: >=1056 float2 scratch. 2 block syncs.
__device__ __forceinline__ void fft1024(float2* a, float2* T, int r, float2 wr, float2 wq){
  float2 p[16];
  dft16(a);
  build_pows(wr, p);
  #pragma unroll
  for (int k=1;k<16;k++) a[k]=cmul(a[k],p[k]);
  #pragma unroll
  for (int k=0;k<16;k++) T[k*66+r]=a[k];
  __syncthreads();
  int k1=r>>2, q=r&3;
  #pragma unroll
  for (int m=0;m<16;m++) a[m]=T[k1*66+4*m+q];
  __syncthreads();
  dft16(a);
  build_pows(wq, p);
  #pragma unroll
  for (int k=1;k<16;k++) a[k]=cmul(a[k],p[k]);
  bool b2=(q&2)!=0, b1=(q&1)!=0, b3=(q==3);
  #pragma unroll
  for (int k=0;k<16;k++){
    float2 v=a[k];
    float2 pp=shflx(v,2);
    float2 A = b2 ? csub(pp,v) : cadd(v,pp);
    A = b3 ? cmnegi(A) : A;
    float2 p2=shflx(A,1);
    a[k] = b1 ? csub(p2,A) : cadd(A,p2);
  }
}

// ---------------- K1: stats, 4-way channel-split (+ twiddles piggybacked) ----------------
__global__ __launch_bounds__(256) void k_stats(const float* __restrict__ x){
  __shared__ float ss[2][256];
  int t = threadIdx.x;
  int lsub = t & 63, cs = t >> 6;
  int l = blockIdx.x*64 + lsub;
  int b = blockIdx.y;
  if (b == 0 && blockIdx.x < 8){   // 8 blocks * 256 = 2048 threads build tables
    int tg = blockIdx.x*256 + t;
    if (tg < 1024){
      double sd, cd; sincospi(-2.0*(double)tg/1024.0, &sd, &cd);
      g_tw1024[tg] = make_float2((float)cd, (float)sd);
    } else {
      int f = tg - 1024;
      double sd, cd; sincospi(-(double)f/1024.0, &sd, &cd);
      g_tw2048[f] = make_float2((float)cd, (float)sd);
    }
    if (tg == 0) g_tw2048[1024] = make_float2(-1.f, 0.f);
  }
  const float* p = x + (size_t)b*C_*L_ + (size_t)cs*128*L_ + l;
  float s = 0.f, s2 = 0.f;
  #pragma unroll 8
  for (int c = 0; c < 128; c++){
    float v = p[(size_t)c*L_];
    s += v; s2 += v*v;
  }
  ss[0][t] = s; ss[1][t] = s2;
  __syncthreads();
  if (cs == 0){
    float S  = ss[0][lsub] + ss[0][64+lsub] + ss[0][128+lsub] + ss[0][192+lsub];
    float S2 = ss[1][lsub] + ss[1][64+lsub] + ss[1][128+lsub] + ss[1][192+lsub];
    float mean = S * (1.0f/C_);
    float var  = (S2 - S*S*(1.0f/C_)) * (1.0f/(C_-1)) + 1e-5f;
    g_mean[b*L_+l] = mean;
    g_rstd[b*L_+l] = rsqrtf(var);
  }
}

// ---------------- K2: spectra -> fp16 cache + |X| sums -> partial gating logits ----------------
__global__ __launch_bounds__(TPB) void k_spec(const float* __restrict__ x,
                                              const float* __restrict__ gw){
  extern __shared__ float2 smraw[];
  float2* T   = smraw;            // 2*1088
  float2* m2  = T + 2176;         // 1024
  float2* r2v = m2 + 1024;        // 1024
  float*  acc = (float*)(r2v + 1024); // 1025
  __shared__ float sred[NE][4];
  int t=threadIdx.x, s=t>>6, r=t&63;
  int b=blockIdx.y, grp=blockIdx.x;
  float2* Ts = T + s*1088;
  const float2* gm2=(const float2*)(g_mean + b*L_);
  const float2* gr2=(const float2*)(g_rstd + b*L_);
  for (int i=t;i<1024;i+=TPB){ m2[i]=gm2[i]; r2v[i]=gr2[i]; }
  for (int i=t;i<F_;i+=TPB) acc[i]=0.f;
  float2 wr=g_tw1024[r];
  float2 wq=g_tw1024[(r&3)<<4];
  __syncthreads();

  for (int it=0; it<4; it++){
    int c = grp*8 + it*2 + s;
    size_t row = (size_t)(b*C_+c);
    const float2* xr = (const float2*)(x + row*L_);
    float2 a[16];
    #pragma unroll
    for (int j=0;j<16;j++){
      int n=(j<<6)+r;
      float2 v=xr[n], mm=m2[n], rr=r2v[n];
      a[j]=make_float2((v.x-mm.x)*rr.x,(v.y-mm.y)*rr.y);
    }
    fft1024(a, Ts, r, wr, wq);
    // spectrum -> smem (own slots) AND fp16 gmem cache (coalesced, slot-linear)
    __half2* gsr = g_spec + row*1024;
    #pragma unroll
    for (int k=0;k<16;k++){
      Ts[k*66+r]=a[k];
      gsr[(k<<6)+r]=__float22half2_rn(a[k]);
    }
    __syncthreads();

    #pragma unroll
    for (int i=0;i<4;i++){
      int f = t + (i<<7);
      if (f==0){
        #pragma unroll
        for (int s2=0;s2<2;s2++){
          float2 z0=T[s2*1088 + 0];
          acc[0]    += fabsf(z0.x+z0.y);
          acc[1024] += fabsf(z0.x-z0.y);
          float2 zh=T[s2*1088 + 1];           // slotf(512)=1
          acc[512]  += sqrtf(zh.x*zh.x+zh.y*zh.y);
        }
      } else {
        int pa=slotf(f), pb=slotf(1024-f);
        float2 W=g_tw2048[f];
        float sa=0.f, sb=0.f;
        #pragma unroll
        for (int s2=0;s2<2;s2++){
          float2 Zf=T[s2*1088+pa], Zg=T[s2*1088+pb];
          float Ex=0.5f*(Zf.x+Zg.x), Ey=0.5f*(Zf.y-Zg.y);
          float Ox=0.5f*(Zf.y+Zg.y), Oy=-0.5f*(Zf.x-Zg.x);
          float WOx=Ox*W.x-Oy*W.y, WOy=Ox*W.y+Oy*W.x;
          float Xax=Ex+WOx, Xay=Ey+WOy;
          float Xbx=Ex-WOx, Xby=Ey-WOy;
          sa += sqrtf(Xax*Xax+Xay*Xay);
          sb += sqrtf(Xbx*Xbx+Xby*Xby);
        }
        acc[f]      += sa;
        acc[1024-f] += sb;
      }
    }
    __syncthreads();
  }

  // partial gating logits for this row-group: pe[e] = sum_f acc[f]*gw[e,f]
  float pe[NE];
  #pragma unroll
  for (int e=0;e<NE;e++) pe[e]=0.f;
  for (int f=t; f<F_; f+=TPB){
    float gi=acc[f];
    #pragma unroll
    for (int e=0;e<NE;e++) pe[e]+=gi*gw[e*F_+f];
  }
  #pragma unroll
  for (int e=0;e<NE;e++){
    float v=pe[e];
    #pragma unroll
    for (int o=16;o;o>>=1) v += __shfl_xor_sync(0xffffffffu, v, o);
    if ((t&31)==0) sred[e][t>>5]=v;
  }
  __syncthreads();
  if (t < NE){
    float sum = sred[t][0]+sred[t][1]+sred[t][2]+sred[t][3];
    g_lp[(b*GROUPS+grp)*NE + t] = sum;
  }
}

// ---------------- K3: inline gating -> prefetched fp16 spectrum -> filter -> inv FFT -> denorm ----------------
__global__ __launch_bounds__(TPB) void k_main(const float* __restrict__ bb,
                                              const float* __restrict__ gb,
                                              float* __restrict__ out){
  extern __shared__ float2 smraw[];
  float2* T   = smraw;            // 2*1088 (spectrum / transpose / time staging)
  float2* N   = T + 2176;         // 2*1024 (conj(Z') natural layout)
  float2* m2  = N + 2048;         // 1024
  float2* r2v = m2 + 1024;        // 1024
  float*  sw  = (float*)(r2v + 1024); // 1025
  __shared__ float spart[64];
  __shared__ float ssc[NE];
  __shared__ int   sidx[NE+1];
  int t=threadIdx.x, s=t>>6, r=t&63;
  int b=blockIdx.y, grp=blockIdx.x;
  float2* Ts = T + s*1088;
  float2* Nsl = N + s*1024;
  const float2* gm2=(const float2*)(g_mean + b*L_);
  const float2* gr2=(const float2*)(g_rstd + b*L_);
  for (int i=t;i<1024;i+=TPB){ m2[i]=gm2[i]; r2v[i]=gr2[i]; }
  // gating reduction: 64 threads, each sums 8 groups for one expert
  if (t < 64){
    int e = t & 7, gc = t >> 3;
    float sacc = 0.f;
    #pragma unroll
    for (int g=0; g<8; g++) sacc += g_lp[(b*GROUPS + gc*8 + g)*NE + e];
    spart[t] = sacc;
  }
  float2 wr=g_tw1024[r];
  float2 wq=g_tw1024[(r&3)<<4];
  __syncthreads();
  if (t == 0){
    float lg[NE]; float mx=-1e30f;
    #pragma unroll
    for (int e=0;e<NE;e++){
      float sm=0.f;
      #pragma unroll
      for (int gc=0;gc<8;gc++) sm += spart[gc*8+e];
      lg[e]=sm*(1.0f/C_)+gb[e];
      mx=fmaxf(mx,lg[e]);
    }
    float sum=0.f;
    #pragma unroll
    for (int e=0;e<NE;e++){ lg[e]=expf(lg[e]-mx); sum+=lg[e]; }
    float inv=1.0f/sum;
    #pragma unroll
    for (int e=0;e<NE;e++) ssc[e]=lg[e]*inv;
    float bnd[NE-1];
    #pragma unroll
    for (int i=0;i<NE-1;i++) bnd[i]=1.0f/(1.0f+expf(-bb[i]));
    for (int i=1;i<NE-1;i++){            // ascending insertion sort
      float key=bnd[i]; int k=i-1;
      while (k>=0 && bnd[k]>key){ bnd[k+1]=bnd[k]; k--; }
      bnd[k+1]=key;
    }
    sidx[0]=0;
    #pragma unroll
    for (int i=0;i<NE-1;i++) sidx[i+1]=(int)(bnd[i]*(float)F_);
    sidx[NE]=F_;
  }
  __syncthreads();
  for (int f=t; f<F_; f+=TPB){
    float w=0.f;
    #pragma unroll
    for (int e=0;e<NE;e++)
      if (f>=sidx[e] && f<sidx[e+1]) w+=ssc[e];
    sw[f]=w;
  }
  __syncthreads();

  const float sc = 1.0f/2048.0f;  // 1/2 (real pack) * 1/1024 (ifft)
  size_t row0 = (size_t)(b*C_ + grp*8 + s);
  // prefetch iteration 0's spectrum into registers
  __half2 pre[16];
  {
    const __half2* gsr = g_spec + row0*1024;
    #pragma unroll
    for (int k=0;k<16;k++) pre[k] = gsr[(k<<6)+r];
  }
  for (int it=0; it<4; it++){
    size_t row = row0 + it*2;
    // prefetched spectrum -> conflict-free smem columns
    #pragma unroll
    for (int k=0;k<16;k++) Ts[k*66+r] = __half22float2(pre[k]);
    __syncthreads();

    // filter: unpack -> Y=w*X -> repack Z' -> write conj(Z') to N (natural order)
    #pragma unroll
    for (int i=0;i<4;i++){
      int f = t + (i<<7);
      if (f==0){
        #pragma unroll
        for (int s2=0;s2<2;s2++){
          float2 z0=T[s2*1088 + 0];
          float X0=z0.x+z0.y, X1=z0.x-z0.y;
          float Y0=sw[0]*X0, Y1=sw[1024]*X1;
          N[s2*1024 + 0]   = make_float2(sc*(Y0+Y1), -sc*(Y0-Y1));
          float wh = sw[512]*(1.0f/1024.0f);
          float2 zh=T[s2*1088 + 1];           // slotf(512)=1
          N[s2*1024 + 512] = make_float2(zh.x*wh, -zh.y*wh);
        }
      } else {
        int pa=slotf(f), pb=slotf(1024-f);
        float wa=sw[f], wb=sw[1024-f];
        float2 W =g_tw2048[f];
        float2 W2=g_tw2048[1024-f];
        #pragma unroll
        for (int s2=0;s2<2;s2++){
          float2 Zf=T[s2*1088+pa], Zg=T[s2*1088+pb];
          float Ex=0.5f*(Zf.x+Zg.x), Ey=0.5f*(Zf.y-Zg.y);
          float Ox=0.5f*(Zf.y+Zg.y), Oy=-0.5f*(Zf.x-Zg.x);
          float WOx=Ox*W.x-Oy*W.y, WOy=Ox*W.y+Oy*W.x;
          float Yax=wa*(Ex+WOx), Yay=wa*(Ey+WOy);
          float Ybx=wb*(Ex-WOx), Yby=wb*(-(Ey-WOy));
          float Ax=Yax+Ybx, Ay=Yay-Yby;
          float Bx=Yax-Ybx, By=Yay+Yby;
          float Cx=Bx*W.x+By*W.y, Cy=By*W.x-Bx*W.y;
          N[s2*1024 + f]      = make_float2(sc*(Ax-Cy), -sc*(Ay+Cx));
          float A2x=Ybx+Yax, A2y=Yby-Yay;
          float B2x=Ybx-Yax, B2y=Yby+Yay;
          float C2x=B2x*W2.x+B2y*W2.y, C2y=B2y*W2.x-B2x*W2.y;
          N[s2*1024 + 1024-f] = make_float2(sc*(A2x-C2y), -sc*(A2y+C2x));
        }
      }
    }
    __syncthreads();

    // inverse FFT via conjugation trick: ifft(Z') = conj(fft(conj(Z')))
    float2 a[16];
    #pragma unroll
    for (int j=0;j<16;j++) a[j]=Nsl[(j<<6)+r];
    fft1024(a, Ts, r, wr, wq);

    // prefetch NEXT iteration's spectrum while staging/denorm hide the latency
    if (it < 3){
      const __half2* gsn = g_spec + (row + 2)*1024;
      #pragma unroll
      for (int k=0;k<16;k++) pre[k] = gsn[(k<<6)+r];
    }

    // stage time samples (conjugated) into Ts at padded natural index
    {
      int k1=r>>2, kb=br2(r&3);
      int base = k1 + 264*kb;                  // n + 8*(n>>8), n = k1+16k+256kb
      #pragma unroll
      for (int k=0;k<16;k++)
        Ts[base + (k<<4)] = make_float2(a[k].x, -a[k].y);
    }
    __syncthreads();

    // de-normalize + coalesced store (stats from smem)
    float4* orow = (float4*)(out + row*L_);
    #pragma unroll
    for (int cc=0; cc<8; cc++){
      int i4 = (cc<<6) + r;                    // float4 index in row
      int n0 = i4<<1;
      int u  = n0 + ((n0>>8)<<3);
      float2 y0=Ts[u], y1=Ts[u+1];
      float2 mm0=m2[n0], mm1=m2[n0+1], rr0=r2v[n0], rr1=r2v[n0+1];
      float4 o;
      o.x=__fdividef(y0.x, rr0.x)+mm0.x;
      o.y=__fdividef(y0.y, rr0.y)+mm0.y;
      o.z=__fdividef(y1.x, rr1.x)+mm1.x;
      o.w=__fdividef(y1.y, rr1.y)+mm1.y;
      orow[i4]=o;
    }
    __syncthreads();
  }
}

// ---------------- launch ----------------
extern "C" void kernel_launch(void* const* d_in, const int* in_sizes, int n_in,
                              void* d_out, int out_size){
  const float* x  = (const float*)d_in[0];
  const float* bb = (const float*)d_in[1];
  const float* gw = (const float*)d_in[2];
  const float* gb = (const float*)d_in[3];
  float* out = (float*)d_out;

  const int SM_SPEC = (2176+1024+1024)*sizeof(float2) + F_*sizeof(float);        // ~37.9KB
  const int SM_MAIN = (2176+2048+1024+1024)*sizeof(float2) + F_*sizeof(float);   // ~54.3KB
  cudaFuncSetAttribute(k_spec, cudaFuncAttributeMaxDynamicSharedMemorySize, SM_SPEC);
  cudaFuncSetAttribute(k_main, cudaFuncAttributeMaxDynamicSharedMemorySize, SM_MAIN);

  k_stats<<<dim3(L_/64, B_), 256>>>(x);
  k_spec<<<dim3(GROUPS, B_), TPB, SM_SPEC>>>(x, gw);
  k_main<<<dim3(GROUPS, B_), TPB, SM_MAIN>>>(bb, gb, out);
}